// round 7
// baseline (speedup 1.0000x reference)
#include <cuda_runtime.h>

typedef unsigned long long ull;

// ---------------------------------------------------------------------------
// f32x2 packed FMA helpers (Blackwell): 2x fp32 FMA throughput vs FFMA-3reg
// ---------------------------------------------------------------------------
__device__ __forceinline__ ull ffma2(ull a, ull b, ull c) {
    ull d;
    asm("fma.rn.f32x2 %0, %1, %2, %3;" : "=l"(d) : "l"(a), "l"(b), "l"(c));
    return d;
}
__device__ __forceinline__ ull pack2(float lo, float hi) {
    ull d;
    asm("mov.b64 %0, {%1, %2};" : "=l"(d) : "f"(lo), "f"(hi));
    return d;
}
__device__ __forceinline__ float2 unpack2(ull v) {
    float2 r;
    asm("mov.b64 {%0, %1}, %2;" : "=f"(r.x), "=f"(r.y) : "l"(v));
    return r;
}

// ---------------------------------------------------------------------------
// Problem constants
// ---------------------------------------------------------------------------
#define B_    128
#define T_    20
#define C_    4
#define HW_   4096
#define D_    128
#define HEADS 8
#define DH    4

#define M_TOT (B_ * T_ * C_)   // 10240
#define K_TOT HW_              // 4096
#define N_TOT D_               // 128

// scratch (device globals; no allocation allowed)
__device__ float g_h[M_TOT * N_TOT];    // activations [b][t][c][d]
__device__ float g_ot[M_TOT * N_TOT];   // out_t scratch, same layout

// ---------------------------------------------------------------------------
// Kernel 1: fused noise-add + embedding GEMM + bias + leaky
//   M=10240, K=4096, N=128.  BM=64, BN=128, BK=16, 256 threads,
//   double-buffered smem, FFMA2 inner loop (thread tile 8x4 as 4 row-pairs).
// ---------------------------------------------------------------------------
#define BM   64
#define BK   16
#define APAD 66

__global__ __launch_bounds__(256, 2) void emb_kernel(
    const float* __restrict__ X, const float* __restrict__ N1,
    const float* __restrict__ N2, const float* __restrict__ W,
    const float* __restrict__ Bias)
{
    __shared__ float As[2][BK][APAD];
    __shared__ float Bs[2][BK][N_TOT];

    const int tid = threadIdx.x;
    const int m0  = blockIdx.x * BM;
    const int rg  = tid >> 5;   // warp id = row group (8 rows)
    const int cg  = tid & 31;   // col group (4 cols)

    // A staging: 256 slots = 64 rows x 4 float4 (BK=16 floats per row)
    const int ar = tid >> 2;    // 0..63 row in tile
    const int af = tid & 3;     // 0..3  float4 within BK
    const long aBase = (long)(m0 + ar) * K_TOT + af * 4;
    // B staging: 2 slots per thread (16 x 128 floats)
    const int bk0 = tid >> 5;   // 0..7
    const int bc0 = tid & 31;
    const long bBase = (long)bk0 * N_TOT + bc0 * 4;

    float4 ax, an1, an2, bw0, bw1;
    ull acc[4][4];
#pragma unroll
    for (int p = 0; p < 4; p++)
#pragma unroll
        for (int j = 0; j < 4; j++) acc[p][j] = 0ull;

#define LOAD_TILE(kt) do {                                     \
        long off = aBase + (long)(kt) * BK;                    \
        ax  = *(const float4*)(X  + off);                      \
        an1 = *(const float4*)(N1 + off);                      \
        an2 = *(const float4*)(N2 + off);                      \
        long wo = bBase + (long)(kt) * BK * N_TOT;             \
        bw0 = *(const float4*)(W + wo);                        \
        bw1 = *(const float4*)(W + wo + 8 * N_TOT);            \
    } while (0)

#define STORE_TILE(bufi) do {                                              \
        As[bufi][af*4+0][ar] = ax.x + 1e-3f*an1.x + 1e-4f*an2.x;           \
        As[bufi][af*4+1][ar] = ax.y + 1e-3f*an1.y + 1e-4f*an2.y;           \
        As[bufi][af*4+2][ar] = ax.z + 1e-3f*an1.z + 1e-4f*an2.z;           \
        As[bufi][af*4+3][ar] = ax.w + 1e-3f*an1.w + 1e-4f*an2.w;           \
        *(float4*)&Bs[bufi][bk0    ][bc0*4] = bw0;                         \
        *(float4*)&Bs[bufi][bk0 + 8][bc0*4] = bw1;                         \
    } while (0)

    LOAD_TILE(0);
    STORE_TILE(0);
    __syncthreads();

    const int NT = K_TOT / BK;  // 256
    for (int kt = 0; kt < NT; kt++) {
        const int buf = kt & 1;
        if (kt + 1 < NT) LOAD_TILE(kt + 1);
#pragma unroll
        for (int kk = 0; kk < BK; kk++) {
            float2 a0 = *(const float2*)&As[buf][kk][rg*8 + 0];
            float2 a1 = *(const float2*)&As[buf][kk][rg*8 + 2];
            float2 a2 = *(const float2*)&As[buf][kk][rg*8 + 4];
            float2 a3 = *(const float2*)&As[buf][kk][rg*8 + 6];
            float4 b  = *(const float4*)&Bs[buf][kk][cg*4];
            ull ap0 = pack2(a0.x, a0.y), ap1 = pack2(a1.x, a1.y);
            ull ap2 = pack2(a2.x, a2.y), ap3 = pack2(a3.x, a3.y);
            ull bp0 = pack2(b.x, b.x), bp1 = pack2(b.y, b.y);
            ull bp2 = pack2(b.z, b.z), bp3 = pack2(b.w, b.w);
            acc[0][0] = ffma2(ap0, bp0, acc[0][0]);
            acc[0][1] = ffma2(ap0, bp1, acc[0][1]);
            acc[0][2] = ffma2(ap0, bp2, acc[0][2]);
            acc[0][3] = ffma2(ap0, bp3, acc[0][3]);
            acc[1][0] = ffma2(ap1, bp0, acc[1][0]);
            acc[1][1] = ffma2(ap1, bp1, acc[1][1]);
            acc[1][2] = ffma2(ap1, bp2, acc[1][2]);
            acc[1][3] = ffma2(ap1, bp3, acc[1][3]);
            acc[2][0] = ffma2(ap2, bp0, acc[2][0]);
            acc[2][1] = ffma2(ap2, bp1, acc[2][1]);
            acc[2][2] = ffma2(ap2, bp2, acc[2][2]);
            acc[2][3] = ffma2(ap2, bp3, acc[2][3]);
            acc[3][0] = ffma2(ap3, bp0, acc[3][0]);
            acc[3][1] = ffma2(ap3, bp1, acc[3][1]);
            acc[3][2] = ffma2(ap3, bp2, acc[3][2]);
            acc[3][3] = ffma2(ap3, bp3, acc[3][3]);
        }
        if (kt + 1 < NT) {
            __syncthreads();
            STORE_TILE(buf ^ 1);
            __syncthreads();
        }
    }

#pragma unroll
    for (int j = 0; j < 4; j++) {
        const int n = cg * 4 + j;
        const float bia = Bias[n];
#pragma unroll
        for (int p = 0; p < 4; p++) {
            float2 v = unpack2(acc[p][j]);
            const int r = m0 + rg * 8 + 2 * p;
            float y0 = v.x + bia; y0 = (y0 > 0.f) ? y0 : 0.2f * y0;
            float y1 = v.y + bia; y1 = (y1 > 0.f) ? y1 : 0.2f * y1;
            g_h[r * N_TOT + n]       = y0;
            g_h[(r + 1) * N_TOT + n] = y1;
        }
    }
#undef LOAD_TILE
#undef STORE_TILE
}

// ---------------------------------------------------------------------------
// Attention shared-memory layout (dynamic smem, 86528 bytes)
// ---------------------------------------------------------------------------
#define SMEM_ATTN_FLOATS (2560 + 4096 + 8192 + 4096 + 128 + 640 + 640 + 640 + 640)
#define SMEM_ATTN_BYTES  (SMEM_ATTN_FLOATS * 4)

// ---------------------------------------------------------------------------
// Kernel 2: T-axis attention. One block per (b, c) pair. seq len = 20.
//   Writes out_t to g_ot.
// ---------------------------------------------------------------------------
__global__ void attnT_kernel(const float* __restrict__ Wq,
                             const float* __restrict__ Wkv,
                             const float* __restrict__ Wout,
                             const float* __restrict__ Bout)
{
    extern __shared__ float sm[];
    float* xs   = sm;                 // [20][128]
    float* wq   = xs   + 2560;        // [128][32]
    float* wkv  = wq   + 4096;        // [128][64]
    float* wout = wkv  + 8192;        // [32][128]
    float* bo   = wout + 4096;        // [128]
    float* qs   = bo   + 128;         // [20][32]
    float* ks   = qs   + 640;
    float* vs   = ks   + 640;
    float* os   = vs   + 640;

    const int tid = threadIdx.x;
    const int b = blockIdx.x >> 2;
    const int c = blockIdx.x & 3;

    for (int f = tid; f < 640; f += 256) {
        int t = f >> 5, dq = f & 31;
        *(float4*)&xs[t * 128 + dq * 4] =
            *(const float4*)&g_h[((b * T_ + t) * C_ + c) * D_ + dq * 4];
    }
    for (int f = tid; f < 1024; f += 256) ((float4*)wq)[f]   = ((const float4*)Wq)[f];
    for (int f = tid; f < 2048; f += 256) ((float4*)wkv)[f]  = ((const float4*)Wkv)[f];
    for (int f = tid; f < 1024; f += 256) ((float4*)wout)[f] = ((const float4*)Wout)[f];
    if (tid < 128) bo[tid] = Bout[tid];
    __syncthreads();

    // qkv projections: 3 * 20 * 32 = 1920 outputs
    for (int o = tid; o < 1920; o += 256) {
        int which = o / 640, rem = o - which * 640;
        int t = rem >> 5, j = rem & 31;
        const float* w;
        int stride;
        if (which == 0)      { w = &wq[j];        stride = 32; }
        else if (which == 1) { w = &wkv[j];       stride = 64; }
        else                 { w = &wkv[32 + j];  stride = 64; }
        const float* xr = &xs[t * 128];
        float acc = 0.f;
#pragma unroll 8
        for (int d = 0; d < 128; d++) acc += xr[d] * w[d * stride];
        float* dst = (which == 0) ? qs : (which == 1) ? ks : vs;
        dst[t * 32 + j] = acc;
    }
    __syncthreads();

    // attention core: 8 heads x 20 query positions = 160 tasks
    if (tid < 160) {
        int h = tid / 20, t = tid - h * 20;
        const float* qp = &qs[t * 32 + h * 4];
        float p[20];
        float mx = -1e30f;
#pragma unroll
        for (int s = 0; s < 20; s++) {
            const float* kp = &ks[s * 32 + h * 4];
            float d = (qp[0]*kp[0] + qp[1]*kp[1] + qp[2]*kp[2] + qp[3]*kp[3]) * 0.5f;
            p[s] = d;
            mx = fmaxf(mx, d);
        }
        float sum = 0.f;
#pragma unroll
        for (int s = 0; s < 20; s++) { p[s] = __expf(p[s] - mx); sum += p[s]; }
        float inv = 1.f / sum;
        float o0 = 0.f, o1 = 0.f, o2 = 0.f, o3 = 0.f;
#pragma unroll
        for (int s = 0; s < 20; s++) {
            const float* vp = &vs[s * 32 + h * 4];
            float w = p[s] * inv;
            o0 += w * vp[0]; o1 += w * vp[1]; o2 += w * vp[2]; o3 += w * vp[3];
        }
        os[t*32 + h*4 + 0] = o0; os[t*32 + h*4 + 1] = o1;
        os[t*32 + h*4 + 2] = o2; os[t*32 + h*4 + 3] = o3;
    }
    __syncthreads();

    // output projection: 20 * 128 = 2560 outputs
    for (int o = tid; o < 2560; o += 256) {
        int t = o >> 7, n = o & 127;
        const float* op = &os[t * 32];
        float acc = bo[n];
#pragma unroll
        for (int j = 0; j < 32; j++) acc += op[j] * wout[j * 128 + n];
        g_ot[((b * T_ + t) * C_ + c) * D_ + n] = acc;
    }
}

// ---------------------------------------------------------------------------
// Kernel 3: C-axis attention + combine.  One block per (b, t-group-of-5).
//   h = leaky(out_t + out_c), written back to g_h.
// ---------------------------------------------------------------------------
__global__ void attnC_kernel(const float* __restrict__ Wq,
                             const float* __restrict__ Wkv,
                             const float* __restrict__ Wout,
                             const float* __restrict__ Bout)
{
    extern __shared__ float sm[];
    float* xs   = sm;                 // [20][128]  (5 t's x 4 c's)
    float* wq   = xs   + 2560;
    float* wkv  = wq   + 4096;
    float* wout = wkv  + 8192;
    float* bo   = wout + 4096;
    float* qs   = bo   + 128;
    float* ks   = qs   + 640;
    float* vs   = ks   + 640;
    float* os   = vs   + 640;

    const int tid = threadIdx.x;
    const int b  = blockIdx.x >> 2;
    const int tg = blockIdx.x & 3;    // t in [tg*5, tg*5+5)

    for (int f = tid; f < 640; f += 256) {
        int rr = f >> 5, dq = f & 31;           // rr = ti*4 + c
        int ti = rr >> 2, c = rr & 3;
        int t  = tg * 5 + ti;
        *(float4*)&xs[rr * 128 + dq * 4] =
            *(const float4*)&g_h[((b * T_ + t) * C_ + c) * D_ + dq * 4];
    }
    for (int f = tid; f < 1024; f += 256) ((float4*)wq)[f]   = ((const float4*)Wq)[f];
    for (int f = tid; f < 2048; f += 256) ((float4*)wkv)[f]  = ((const float4*)Wkv)[f];
    for (int f = tid; f < 1024; f += 256) ((float4*)wout)[f] = ((const float4*)Wout)[f];
    if (tid < 128) bo[tid] = Bout[tid];
    __syncthreads();

    for (int o = tid; o < 1920; o += 256) {
        int which = o / 640, rem = o - which * 640;
        int rr = rem >> 5, j = rem & 31;
        const float* w;
        int stride;
        if (which == 0)      { w = &wq[j];        stride = 32; }
        else if (which == 1) { w = &wkv[j];       stride = 64; }
        else                 { w = &wkv[32 + j];  stride = 64; }
        const float* xr = &xs[rr * 128];
        float acc = 0.f;
#pragma unroll 8
        for (int d = 0; d < 128; d++) acc += xr[d] * w[d * stride];
        float* dst = (which == 0) ? qs : (which == 1) ? ks : vs;
        dst[rr * 32 + j] = acc;
    }
    __syncthreads();

    // attention over c: 5 t's x 8 heads x 4 queries = 160 tasks
    if (tid < 160) {
        int ti = tid >> 5, r8 = tid & 31;
        int h = r8 >> 2, cq = r8 & 3;
        int rq = ti * 4 + cq;
        const float* qp = &qs[rq * 32 + h * 4];
        float p[4];
        float mx = -1e30f;
#pragma unroll
        for (int s = 0; s < 4; s++) {
            const float* kp = &ks[(ti * 4 + s) * 32 + h * 4];
            float d = (qp[0]*kp[0] + qp[1]*kp[1] + qp[2]*kp[2] + qp[3]*kp[3]) * 0.5f;
            p[s] = d;
            mx = fmaxf(mx, d);
        }
        float sum = 0.f;
#pragma unroll
        for (int s = 0; s < 4; s++) { p[s] = __expf(p[s] - mx); sum += p[s]; }
        float inv = 1.f / sum;
        float o0 = 0.f, o1 = 0.f, o2 = 0.f, o3 = 0.f;
#pragma unroll
        for (int s = 0; s < 4; s++) {
            const float* vp = &vs[(ti * 4 + s) * 32 + h * 4];
            float w = p[s] * inv;
            o0 += w * vp[0]; o1 += w * vp[1]; o2 += w * vp[2]; o3 += w * vp[3];
        }
        os[rq*32 + h*4 + 0] = o0; os[rq*32 + h*4 + 1] = o1;
        os[rq*32 + h*4 + 2] = o2; os[rq*32 + h*4 + 3] = o3;
    }
    __syncthreads();

    // output projection + combine with out_t + leaky, write back to g_h
    for (int o = tid; o < 2560; o += 256) {
        int rr = o >> 7, n = o & 127;
        int ti = rr >> 2, c = rr & 3;
        int t  = tg * 5 + ti;
        const float* op = &os[rr * 32];
        float acc = bo[n];
#pragma unroll
        for (int j = 0; j < 32; j++) acc += op[j] * wout[j * 128 + n];
        int g = ((b * T_ + t) * C_ + c) * D_ + n;
        float u = acc + g_ot[g];
        g_h[g] = (u > 0.f) ? u : 0.2f * u;
    }
}

// ---------------------------------------------------------------------------
// Kernel 4: decoder — per-batch 10240-dot-product + bias + sigmoid
// ---------------------------------------------------------------------------
__global__ void dec_kernel(const float* __restrict__ Wd,
                           const float* __restrict__ bd,
                           float* __restrict__ out)
{
    const int b = blockIdx.x;
    const int tid = threadIdx.x;
    const float* hr = &g_h[b * (T_ * C_ * D_)];
    float acc = 0.f;
    for (int i = tid; i < T_ * C_ * D_; i += 256) acc += hr[i] * Wd[i];
#pragma unroll
    for (int off = 16; off; off >>= 1) acc += __shfl_down_sync(0xffffffffu, acc, off);
    __shared__ float red[8];
    if ((tid & 31) == 0) red[tid >> 5] = acc;
    __syncthreads();
    if (tid == 0) {
        float s = 0.f;
#pragma unroll
        for (int w = 0; w < 8; w++) s += red[w];
        s += bd[0];
        out[b] = 1.f / (1.f + __expf(-s));
    }
}

// ---------------------------------------------------------------------------
// Launch
// ---------------------------------------------------------------------------
extern "C" void kernel_launch(void* const* d_in, const int* in_sizes, int n_in,
                              void* d_out, int out_size)
{
    const float* x     = (const float*)d_in[0];
    const float* n1    = (const float*)d_in[1];
    const float* n2    = (const float*)d_in[2];
    const float* W_emb = (const float*)d_in[3];
    const float* b_emb = (const float*)d_in[4];
    const float* Wq    = (const float*)d_in[5];   // [2][2][128][32]
    const float* Wkv   = (const float*)d_in[6];   // [2][2][128][64]
    const float* Wout  = (const float*)d_in[7];   // [2][2][32][128]
    const float* bout  = (const float*)d_in[8];   // [2][2][128]
    const float* W_dec = (const float*)d_in[9];   // [10240][1]
    const float* b_dec = (const float*)d_in[10];  // [1]
    float* out = (float*)d_out;

    // opt-in dynamic smem (>48KB) for attention kernels; idempotent, capture-safe
    cudaFuncSetAttribute(attnT_kernel, cudaFuncAttributeMaxDynamicSharedMemorySize, SMEM_ATTN_BYTES);
    cudaFuncSetAttribute(attnC_kernel, cudaFuncAttributeMaxDynamicSharedMemorySize, SMEM_ATTN_BYTES);

    emb_kernel<<<M_TOT / BM, 256>>>(x, n1, n2, W_emb, b_emb);

    for (int i = 0; i < 2; i++) {
        const int sT = i * 2 + 0;
        const int sC = i * 2 + 1;
        attnT_kernel<<<B_ * C_, 256, SMEM_ATTN_BYTES>>>(
            Wq + sT * 128 * 32, Wkv + sT * 128 * 64,
            Wout + sT * 32 * 128, bout + sT * 128);
        attnC_kernel<<<B_ * C_, 256, SMEM_ATTN_BYTES>>>(
            Wq + sC * 128 * 32, Wkv + sC * 128 * 64,
            Wout + sC * 32 * 128, bout + sC * 128);
    }

    dec_kernel<<<B_, 256>>>(W_dec, b_dec, out);
}

// round 8
// speedup vs baseline: 1.0030x; 1.0030x over previous
#include <cuda_runtime.h>

typedef unsigned long long ull;

// ---------------------------------------------------------------------------
// f32x2 packed FMA helpers (Blackwell): 2x fp32 FMA throughput vs FFMA-3reg
// ---------------------------------------------------------------------------
__device__ __forceinline__ ull ffma2(ull a, ull b, ull c) {
    ull d;
    asm("fma.rn.f32x2 %0, %1, %2, %3;" : "=l"(d) : "l"(a), "l"(b), "l"(c));
    return d;
}
__device__ __forceinline__ ull pack2(float lo, float hi) {
    ull d;
    asm("mov.b64 %0, {%1, %2};" : "=l"(d) : "f"(lo), "f"(hi));
    return d;
}
__device__ __forceinline__ float2 unpack2(ull v) {
    float2 r;
    asm("mov.b64 {%0, %1}, %2;" : "=f"(r.x), "=f"(r.y) : "l"(v));
    return r;
}

// ---------------------------------------------------------------------------
// Problem constants
// ---------------------------------------------------------------------------
#define B_    128
#define T_    20
#define C_    4
#define HW_   4096
#define D_    128
#define HEADS 8
#define DH    4

#define M_TOT (B_ * T_ * C_)   // 10240
#define K_TOT HW_              // 4096
#define N_TOT D_               // 128

// scratch (device globals; no allocation allowed)
__device__ float g_h[M_TOT * N_TOT];    // activations [b][t][c][d]
__device__ float g_ot[M_TOT * N_TOT];   // out_t scratch, same layout

// ---------------------------------------------------------------------------
// Kernel 1: fused noise-add + embedding GEMM + bias + leaky
//   M=10240, K=4096, N=128.  BM=64, BN=128, BK=16, 256 threads,
//   double-buffered smem, FFMA2 inner loop (thread tile 8x4 as 4 row-pairs).
// ---------------------------------------------------------------------------
#define BM   64
#define BK   16
#define APAD 66

__global__ __launch_bounds__(256, 2) void emb_kernel(
    const float* __restrict__ X, const float* __restrict__ N1,
    const float* __restrict__ N2, const float* __restrict__ W,
    const float* __restrict__ Bias)
{
    __shared__ float As[2][BK][APAD];
    __shared__ float Bs[2][BK][N_TOT];

    const int tid = threadIdx.x;
    const int m0  = blockIdx.x * BM;
    const int rg  = tid >> 5;   // warp id = row group (8 rows)
    const int cg  = tid & 31;   // col group (4 cols)

    // A staging: 256 slots = 64 rows x 4 float4 (BK=16 floats per row)
    const int ar = tid >> 2;    // 0..63 row in tile
    const int af = tid & 3;     // 0..3  float4 within BK
    const long aBase = (long)(m0 + ar) * K_TOT + af * 4;
    // B staging: 2 slots per thread (16 x 128 floats)
    const int bk0 = tid >> 5;   // 0..7
    const int bc0 = tid & 31;
    const long bBase = (long)bk0 * N_TOT + bc0 * 4;

    float4 ax, an1, an2, bw0, bw1;
    ull acc[4][4];
#pragma unroll
    for (int p = 0; p < 4; p++)
#pragma unroll
        for (int j = 0; j < 4; j++) acc[p][j] = 0ull;

#define LOAD_TILE(kt) do {                                     \
        long off = aBase + (long)(kt) * BK;                    \
        ax  = *(const float4*)(X  + off);                      \
        an1 = *(const float4*)(N1 + off);                      \
        an2 = *(const float4*)(N2 + off);                      \
        long wo = bBase + (long)(kt) * BK * N_TOT;             \
        bw0 = *(const float4*)(W + wo);                        \
        bw1 = *(const float4*)(W + wo + 8 * N_TOT);            \
    } while (0)

#define STORE_TILE(bufi) do {                                              \
        As[bufi][af*4+0][ar] = ax.x + 1e-3f*an1.x + 1e-4f*an2.x;           \
        As[bufi][af*4+1][ar] = ax.y + 1e-3f*an1.y + 1e-4f*an2.y;           \
        As[bufi][af*4+2][ar] = ax.z + 1e-3f*an1.z + 1e-4f*an2.z;           \
        As[bufi][af*4+3][ar] = ax.w + 1e-3f*an1.w + 1e-4f*an2.w;           \
        *(float4*)&Bs[bufi][bk0    ][bc0*4] = bw0;                         \
        *(float4*)&Bs[bufi][bk0 + 8][bc0*4] = bw1;                         \
    } while (0)

    LOAD_TILE(0);
    STORE_TILE(0);
    __syncthreads();

    const int NT = K_TOT / BK;  // 256
    for (int kt = 0; kt < NT; kt++) {
        const int buf = kt & 1;
        if (kt + 1 < NT) LOAD_TILE(kt + 1);
#pragma unroll
        for (int kk = 0; kk < BK; kk++) {
            float2 a0 = *(const float2*)&As[buf][kk][rg*8 + 0];
            float2 a1 = *(const float2*)&As[buf][kk][rg*8 + 2];
            float2 a2 = *(const float2*)&As[buf][kk][rg*8 + 4];
            float2 a3 = *(const float2*)&As[buf][kk][rg*8 + 6];
            float4 b  = *(const float4*)&Bs[buf][kk][cg*4];
            ull ap0 = pack2(a0.x, a0.y), ap1 = pack2(a1.x, a1.y);
            ull ap2 = pack2(a2.x, a2.y), ap3 = pack2(a3.x, a3.y);
            ull bp0 = pack2(b.x, b.x), bp1 = pack2(b.y, b.y);
            ull bp2 = pack2(b.z, b.z), bp3 = pack2(b.w, b.w);
            acc[0][0] = ffma2(ap0, bp0, acc[0][0]);
            acc[0][1] = ffma2(ap0, bp1, acc[0][1]);
            acc[0][2] = ffma2(ap0, bp2, acc[0][2]);
            acc[0][3] = ffma2(ap0, bp3, acc[0][3]);
            acc[1][0] = ffma2(ap1, bp0, acc[1][0]);
            acc[1][1] = ffma2(ap1, bp1, acc[1][1]);
            acc[1][2] = ffma2(ap1, bp2, acc[1][2]);
            acc[1][3] = ffma2(ap1, bp3, acc[1][3]);
            acc[2][0] = ffma2(ap2, bp0, acc[2][0]);
            acc[2][1] = ffma2(ap2, bp1, acc[2][1]);
            acc[2][2] = ffma2(ap2, bp2, acc[2][2]);
            acc[2][3] = ffma2(ap2, bp3, acc[2][3]);
            acc[3][0] = ffma2(ap3, bp0, acc[3][0]);
            acc[3][1] = ffma2(ap3, bp1, acc[3][1]);
            acc[3][2] = ffma2(ap3, bp2, acc[3][2]);
            acc[3][3] = ffma2(ap3, bp3, acc[3][3]);
        }
        if (kt + 1 < NT) {
            __syncthreads();
            STORE_TILE(buf ^ 1);
            __syncthreads();
        }
    }

#pragma unroll
    for (int j = 0; j < 4; j++) {
        const int n = cg * 4 + j;
        const float bia = Bias[n];
#pragma unroll
        for (int p = 0; p < 4; p++) {
            float2 v = unpack2(acc[p][j]);
            const int r = m0 + rg * 8 + 2 * p;
            float y0 = v.x + bia; y0 = (y0 > 0.f) ? y0 : 0.2f * y0;
            float y1 = v.y + bia; y1 = (y1 > 0.f) ? y1 : 0.2f * y1;
            g_h[r * N_TOT + n]       = y0;
            g_h[(r + 1) * N_TOT + n] = y1;
        }
    }
#undef LOAD_TILE
#undef STORE_TILE
}

// ---------------------------------------------------------------------------
// Attention shared-memory layout (dynamic smem, 86528 bytes)
// ---------------------------------------------------------------------------
#define SMEM_ATTN_FLOATS (2560 + 4096 + 8192 + 4096 + 128 + 640 + 640 + 640 + 640)
#define SMEM_ATTN_BYTES  (SMEM_ATTN_FLOATS * 4)

// ---------------------------------------------------------------------------
// Kernel 2: T-axis attention. One block per (b, c) pair. seq len = 20.
//   Writes out_t to g_ot.
// ---------------------------------------------------------------------------
__global__ void attnT_kernel(const float* __restrict__ Wq,
                             const float* __restrict__ Wkv,
                             const float* __restrict__ Wout,
                             const float* __restrict__ Bout)
{
    extern __shared__ float sm[];
    float* xs   = sm;                 // [20][128]
    float* wq   = xs   + 2560;        // [128][32]
    float* wkv  = wq   + 4096;        // [128][64]
    float* wout = wkv  + 8192;        // [32][128]
    float* bo   = wout + 4096;        // [128]
    float* qs   = bo   + 128;         // [20][32]
    float* ks   = qs   + 640;
    float* vs   = ks   + 640;
    float* os   = vs   + 640;

    const int tid = threadIdx.x;
    const int b = blockIdx.x >> 2;
    const int c = blockIdx.x & 3;

    for (int f = tid; f < 640; f += 256) {
        int t = f >> 5, dq = f & 31;
        *(float4*)&xs[t * 128 + dq * 4] =
            *(const float4*)&g_h[((b * T_ + t) * C_ + c) * D_ + dq * 4];
    }
    for (int f = tid; f < 1024; f += 256) ((float4*)wq)[f]   = ((const float4*)Wq)[f];
    for (int f = tid; f < 2048; f += 256) ((float4*)wkv)[f]  = ((const float4*)Wkv)[f];
    for (int f = tid; f < 1024; f += 256) ((float4*)wout)[f] = ((const float4*)Wout)[f];
    if (tid < 128) bo[tid] = Bout[tid];
    __syncthreads();

    // qkv projections: 3 * 20 * 32 = 1920 outputs
    for (int o = tid; o < 1920; o += 256) {
        int which = o / 640, rem = o - which * 640;
        int t = rem >> 5, j = rem & 31;
        const float* w;
        int stride;
        if (which == 0)      { w = &wq[j];        stride = 32; }
        else if (which == 1) { w = &wkv[j];       stride = 64; }
        else                 { w = &wkv[32 + j];  stride = 64; }
        const float* xr = &xs[t * 128];
        float acc = 0.f;
#pragma unroll 8
        for (int d = 0; d < 128; d++) acc += xr[d] * w[d * stride];
        float* dst = (which == 0) ? qs : (which == 1) ? ks : vs;
        dst[t * 32 + j] = acc;
    }
    __syncthreads();

    // attention core: 8 heads x 20 query positions = 160 tasks
    if (tid < 160) {
        int h = tid / 20, t = tid - h * 20;
        const float* qp = &qs[t * 32 + h * 4];
        float p[20];
        float mx = -1e30f;
#pragma unroll
        for (int s = 0; s < 20; s++) {
            const float* kp = &ks[s * 32 + h * 4];
            float d = (qp[0]*kp[0] + qp[1]*kp[1] + qp[2]*kp[2] + qp[3]*kp[3]) * 0.5f;
            p[s] = d;
            mx = fmaxf(mx, d);
        }
        float sum = 0.f;
#pragma unroll
        for (int s = 0; s < 20; s++) { p[s] = __expf(p[s] - mx); sum += p[s]; }
        float inv = 1.f / sum;
        float o0 = 0.f, o1 = 0.f, o2 = 0.f, o3 = 0.f;
#pragma unroll
        for (int s = 0; s < 20; s++) {
            const float* vp = &vs[s * 32 + h * 4];
            float w = p[s] * inv;
            o0 += w * vp[0]; o1 += w * vp[1]; o2 += w * vp[2]; o3 += w * vp[3];
        }
        os[t*32 + h*4 + 0] = o0; os[t*32 + h*4 + 1] = o1;
        os[t*32 + h*4 + 2] = o2; os[t*32 + h*4 + 3] = o3;
    }
    __syncthreads();

    // output projection: 20 * 128 = 2560 outputs
    for (int o = tid; o < 2560; o += 256) {
        int t = o >> 7, n = o & 127;
        const float* op = &os[t * 32];
        float acc = bo[n];
#pragma unroll
        for (int j = 0; j < 32; j++) acc += op[j] * wout[j * 128 + n];
        g_ot[((b * T_ + t) * C_ + c) * D_ + n] = acc;
    }
}

// ---------------------------------------------------------------------------
// Kernel 3: C-axis attention + combine.  One block per (b, t-group-of-5).
//   h = leaky(out_t + out_c), written back to g_h.
// ---------------------------------------------------------------------------
__global__ void attnC_kernel(const float* __restrict__ Wq,
                             const float* __restrict__ Wkv,
                             const float* __restrict__ Wout,
                             const float* __restrict__ Bout)
{
    extern __shared__ float sm[];
    float* xs   = sm;                 // [20][128]  (5 t's x 4 c's)
    float* wq   = xs   + 2560;
    float* wkv  = wq   + 4096;
    float* wout = wkv  + 8192;
    float* bo   = wout + 4096;
    float* qs   = bo   + 128;
    float* ks   = qs   + 640;
    float* vs   = ks   + 640;
    float* os   = vs   + 640;

    const int tid = threadIdx.x;
    const int b  = blockIdx.x >> 2;
    const int tg = blockIdx.x & 3;    // t in [tg*5, tg*5+5)

    for (int f = tid; f < 640; f += 256) {
        int rr = f >> 5, dq = f & 31;           // rr = ti*4 + c
        int ti = rr >> 2, c = rr & 3;
        int t  = tg * 5 + ti;
        *(float4*)&xs[rr * 128 + dq * 4] =
            *(const float4*)&g_h[((b * T_ + t) * C_ + c) * D_ + dq * 4];
    }
    for (int f = tid; f < 1024; f += 256) ((float4*)wq)[f]   = ((const float4*)Wq)[f];
    for (int f = tid; f < 2048; f += 256) ((float4*)wkv)[f]  = ((const float4*)Wkv)[f];
    for (int f = tid; f < 1024; f += 256) ((float4*)wout)[f] = ((const float4*)Wout)[f];
    if (tid < 128) bo[tid] = Bout[tid];
    __syncthreads();

    for (int o = tid; o < 1920; o += 256) {
        int which = o / 640, rem = o - which * 640;
        int rr = rem >> 5, j = rem & 31;
        const float* w;
        int stride;
        if (which == 0)      { w = &wq[j];        stride = 32; }
        else if (which == 1) { w = &wkv[j];       stride = 64; }
        else                 { w = &wkv[32 + j];  stride = 64; }
        const float* xr = &xs[rr * 128];
        float acc = 0.f;
#pragma unroll 8
        for (int d = 0; d < 128; d++) acc += xr[d] * w[d * stride];
        float* dst = (which == 0) ? qs : (which == 1) ? ks : vs;
        dst[rr * 32 + j] = acc;
    }
    __syncthreads();

    // attention over c: 5 t's x 8 heads x 4 queries = 160 tasks
    if (tid < 160) {
        int ti = tid >> 5, r8 = tid & 31;
        int h = r8 >> 2, cq = r8 & 3;
        int rq = ti * 4 + cq;
        const float* qp = &qs[rq * 32 + h * 4];
        float p[4];
        float mx = -1e30f;
#pragma unroll
        for (int s = 0; s < 4; s++) {
            const float* kp = &ks[(ti * 4 + s) * 32 + h * 4];
            float d = (qp[0]*kp[0] + qp[1]*kp[1] + qp[2]*kp[2] + qp[3]*kp[3]) * 0.5f;
            p[s] = d;
            mx = fmaxf(mx, d);
        }
        float sum = 0.f;
#pragma unroll
        for (int s = 0; s < 4; s++) { p[s] = __expf(p[s] - mx); sum += p[s]; }
        float inv = 1.f / sum;
        float o0 = 0.f, o1 = 0.f, o2 = 0.f, o3 = 0.f;
#pragma unroll
        for (int s = 0; s < 4; s++) {
            const float* vp = &vs[(ti * 4 + s) * 32 + h * 4];
            float w = p[s] * inv;
            o0 += w * vp[0]; o1 += w * vp[1]; o2 += w * vp[2]; o3 += w * vp[3];
        }
        os[rq*32 + h*4 + 0] = o0; os[rq*32 + h*4 + 1] = o1;
        os[rq*32 + h*4 + 2] = o2; os[rq*32 + h*4 + 3] = o3;
    }
    __syncthreads();

    // output projection + combine with out_t + leaky, write back to g_h
    for (int o = tid; o < 2560; o += 256) {
        int rr = o >> 7, n = o & 127;
        int ti = rr >> 2, c = rr & 3;
        int t  = tg * 5 + ti;
        const float* op = &os[rr * 32];
        float acc = bo[n];
#pragma unroll
        for (int j = 0; j < 32; j++) acc += op[j] * wout[j * 128 + n];
        int g = ((b * T_ + t) * C_ + c) * D_ + n;
        float u = acc + g_ot[g];
        g_h[g] = (u > 0.f) ? u : 0.2f * u;
    }
}

// ---------------------------------------------------------------------------
// Kernel 4: decoder — per-batch 10240-dot-product + bias + sigmoid
// ---------------------------------------------------------------------------
__global__ void dec_kernel(const float* __restrict__ Wd,
                           const float* __restrict__ bd,
                           float* __restrict__ out)
{
    const int b = blockIdx.x;
    const int tid = threadIdx.x;
    const float* hr = &g_h[b * (T_ * C_ * D_)];
    float acc = 0.f;
    for (int i = tid; i < T_ * C_ * D_; i += 256) acc += hr[i] * Wd[i];
#pragma unroll
    for (int off = 16; off; off >>= 1) acc += __shfl_down_sync(0xffffffffu, acc, off);
    __shared__ float red[8];
    if ((tid & 31) == 0) red[tid >> 5] = acc;
    __syncthreads();
    if (tid == 0) {
        float s = 0.f;
#pragma unroll
        for (int w = 0; w < 8; w++) s += red[w];
        s += bd[0];
        out[b] = 1.f / (1.f + __expf(-s));
    }
}

// ---------------------------------------------------------------------------
// Launch
// ---------------------------------------------------------------------------
extern "C" void kernel_launch(void* const* d_in, const int* in_sizes, int n_in,
                              void* d_out, int out_size)
{
    const float* x     = (const float*)d_in[0];
    const float* n1    = (const float*)d_in[1];
    const float* n2    = (const float*)d_in[2];
    const float* W_emb = (const float*)d_in[3];
    const float* b_emb = (const float*)d_in[4];
    const float* Wq    = (const float*)d_in[5];   // [2][2][128][32]
    const float* Wkv   = (const float*)d_in[6];   // [2][2][128][64]
    const float* Wout  = (const float*)d_in[7];   // [2][2][32][128]
    const float* bout  = (const float*)d_in[8];   // [2][2][128]
    const float* W_dec = (const float*)d_in[9];   // [10240][1]
    const float* b_dec = (const float*)d_in[10];  // [1]
    float* out = (float*)d_out;

    // opt-in dynamic smem (>48KB) for attention kernels; idempotent, capture-safe
    cudaFuncSetAttribute(attnT_kernel, cudaFuncAttributeMaxDynamicSharedMemorySize, SMEM_ATTN_BYTES);
    cudaFuncSetAttribute(attnC_kernel, cudaFuncAttributeMaxDynamicSharedMemorySize, SMEM_ATTN_BYTES);

    emb_kernel<<<M_TOT / BM, 256>>>(x, n1, n2, W_emb, b_emb);

    for (int i = 0; i < 2; i++) {
        const int sT = i * 2 + 0;
        const int sC = i * 2 + 1;
        attnT_kernel<<<B_ * C_, 256, SMEM_ATTN_BYTES>>>(
            Wq + sT * 128 * 32, Wkv + sT * 128 * 64,
            Wout + sT * 32 * 128, bout + sT * 128);
        attnC_kernel<<<B_ * C_, 256, SMEM_ATTN_BYTES>>>(
            Wq + sC * 128 * 32, Wkv + sC * 128 * 64,
            Wout + sC * 32 * 128, bout + sC * 128);
    }

    dec_kernel<<<B_, 256>>>(W_dec, b_dec, out);
}

// round 9
// speedup vs baseline: 1.4698x; 1.4654x over previous
#include <cuda_runtime.h>

typedef unsigned long long ull;

// ---------------------------------------------------------------------------
// f32x2 packed FMA helpers
// ---------------------------------------------------------------------------
__device__ __forceinline__ ull ffma2(ull a, ull b, ull c) {
    ull d;
    asm("fma.rn.f32x2 %0, %1, %2, %3;" : "=l"(d) : "l"(a), "l"(b), "l"(c));
    return d;
}
__device__ __forceinline__ ull pack2(float lo, float hi) {
    ull d;
    asm("mov.b64 %0, {%1, %2};" : "=l"(d) : "f"(lo), "f"(hi));
    return d;
}
__device__ __forceinline__ float2 unpack2(ull v) {
    float2 r;
    asm("mov.b64 {%0, %1}, %2;" : "=f"(r.x), "=f"(r.y) : "l"(v));
    return r;
}

// ---------------------------------------------------------------------------
// Problem constants
// ---------------------------------------------------------------------------
#define B_    128
#define T_    20
#define C_    4
#define HW_   4096
#define D_    128

#define M_TOT (B_ * T_ * C_)   // 10240
#define K_TOT HW_              // 4096
#define N_TOT D_               // 128

#define KSPLIT 2
#define KSEG   (K_TOT / KSPLIT)   // 2048

// scratch: un-activated GEMM partials [split][M][128]
__device__ float g_part[KSPLIT * M_TOT * N_TOT];

// ---------------------------------------------------------------------------
// Kernel 1: fused noise-add + embedding GEMM (K-split partial sums)
//   grid (160, 2): blockIdx.x = m-tile, blockIdx.y = K segment.
// ---------------------------------------------------------------------------
#define BM   64
#define BK   16
#define APAD 66

__global__ __launch_bounds__(256, 3) void emb_kernel(
    const float* __restrict__ X, const float* __restrict__ N1,
    const float* __restrict__ N2, const float* __restrict__ W)
{
    __shared__ float As[2][BK][APAD];
    __shared__ float Bs[2][BK][N_TOT];

    const int tid = threadIdx.x;
    const int m0  = blockIdx.x * BM;
    const int ks0 = blockIdx.y * KSEG;
    const int rg  = tid >> 5;   // warp id = row group (8 rows)
    const int cg  = tid & 31;   // col group (4 cols)

    const int ar = tid >> 2;    // 0..63 row in tile
    const int af = tid & 3;     // 0..3  float4 within BK
    const long aBase = (long)(m0 + ar) * K_TOT + ks0 + af * 4;
    const int bk0 = tid >> 5;   // 0..7
    const int bc0 = tid & 31;
    const long bBase = (long)(ks0 + bk0) * N_TOT + bc0 * 4;

    float4 ax, an1, an2, bw0, bw1;
    ull acc[4][4];
#pragma unroll
    for (int p = 0; p < 4; p++)
#pragma unroll
        for (int j = 0; j < 4; j++) acc[p][j] = 0ull;

#define LOAD_TILE(kt) do {                                     \
        long off = aBase + (long)(kt) * BK;                    \
        ax  = *(const float4*)(X  + off);                      \
        an1 = *(const float4*)(N1 + off);                      \
        an2 = *(const float4*)(N2 + off);                      \
        long wo = bBase + (long)(kt) * BK * N_TOT;             \
        bw0 = *(const float4*)(W + wo);                        \
        bw1 = *(const float4*)(W + wo + 8 * N_TOT);            \
    } while (0)

#define STORE_TILE(bufi) do {                                              \
        As[bufi][af*4+0][ar] = ax.x + 1e-3f*an1.x + 1e-4f*an2.x;           \
        As[bufi][af*4+1][ar] = ax.y + 1e-3f*an1.y + 1e-4f*an2.y;           \
        As[bufi][af*4+2][ar] = ax.z + 1e-3f*an1.z + 1e-4f*an2.z;           \
        As[bufi][af*4+3][ar] = ax.w + 1e-3f*an1.w + 1e-4f*an2.w;           \
        *(float4*)&Bs[bufi][bk0    ][bc0*4] = bw0;                         \
        *(float4*)&Bs[bufi][bk0 + 8][bc0*4] = bw1;                         \
    } while (0)

    LOAD_TILE(0);
    STORE_TILE(0);
    __syncthreads();

    const int NT = KSEG / BK;  // 128
    for (int kt = 0; kt < NT; kt++) {
        const int buf = kt & 1;
        if (kt + 1 < NT) LOAD_TILE(kt + 1);
#pragma unroll
        for (int kk = 0; kk < BK; kk++) {
            float2 a0 = *(const float2*)&As[buf][kk][rg*8 + 0];
            float2 a1 = *(const float2*)&As[buf][kk][rg*8 + 2];
            float2 a2 = *(const float2*)&As[buf][kk][rg*8 + 4];
            float2 a3 = *(const float2*)&As[buf][kk][rg*8 + 6];
            float4 b  = *(const float4*)&Bs[buf][kk][cg*4];
            ull ap0 = pack2(a0.x, a0.y), ap1 = pack2(a1.x, a1.y);
            ull ap2 = pack2(a2.x, a2.y), ap3 = pack2(a3.x, a3.y);
            ull bp0 = pack2(b.x, b.x), bp1 = pack2(b.y, b.y);
            ull bp2 = pack2(b.z, b.z), bp3 = pack2(b.w, b.w);
            acc[0][0] = ffma2(ap0, bp0, acc[0][0]);
            acc[0][1] = ffma2(ap0, bp1, acc[0][1]);
            acc[0][2] = ffma2(ap0, bp2, acc[0][2]);
            acc[0][3] = ffma2(ap0, bp3, acc[0][3]);
            acc[1][0] = ffma2(ap1, bp0, acc[1][0]);
            acc[1][1] = ffma2(ap1, bp1, acc[1][1]);
            acc[1][2] = ffma2(ap1, bp2, acc[1][2]);
            acc[1][3] = ffma2(ap1, bp3, acc[1][3]);
            acc[2][0] = ffma2(ap2, bp0, acc[2][0]);
            acc[2][1] = ffma2(ap2, bp1, acc[2][1]);
            acc[2][2] = ffma2(ap2, bp2, acc[2][2]);
            acc[2][3] = ffma2(ap2, bp3, acc[2][3]);
            acc[3][0] = ffma2(ap3, bp0, acc[3][0]);
            acc[3][1] = ffma2(ap3, bp1, acc[3][1]);
            acc[3][2] = ffma2(ap3, bp2, acc[3][2]);
            acc[3][3] = ffma2(ap3, bp3, acc[3][3]);
        }
        if (kt + 1 < NT) {
            __syncthreads();
            STORE_TILE(buf ^ 1);
            __syncthreads();
        }
    }

    float* gp = g_part + (size_t)blockIdx.y * (M_TOT * N_TOT);
#pragma unroll
    for (int j = 0; j < 4; j++) {
        const int n = cg * 4 + j;
#pragma unroll
        for (int p = 0; p < 4; p++) {
            float2 v = unpack2(acc[p][j]);
            const int r = m0 + rg * 8 + 2 * p;
            gp[r * N_TOT + n]       = v.x;
            gp[(r + 1) * N_TOT + n] = v.y;
        }
    }
#undef LOAD_TILE
#undef STORE_TILE
}

// ---------------------------------------------------------------------------
// Mega kernel: per-batch fused (partial-combine + 2 axial blocks + decoder).
//   One block per b.  256 threads.  Everything resident in smem.
//   hsT / otT / osT are TRANSPOSED: [col][row], row-stride RP=82 (pad).
// ---------------------------------------------------------------------------
#define RP 82   // padded row stride (80 rows + 2)

#define MEGA_FLOATS (128*RP + 128*RP + 128*96 + 32*128 + 128 + 3*80*32 + 32*RP)
#define MEGA_BYTES  (MEGA_FLOATS * 4)

__global__ __launch_bounds__(256) void mega_kernel(
    const float* __restrict__ Wq,   // [2][2][128][32]
    const float* __restrict__ Wkv,  // [2][2][128][64]
    const float* __restrict__ Wout, // [2][2][32][128]
    const float* __restrict__ Bout, // [2][2][128]
    const float* __restrict__ Bemb, // [128]
    const float* __restrict__ Wd,   // [10240]
    const float* __restrict__ bd,   // [1]
    float* __restrict__ out)
{
    extern __shared__ float sm[];
    float* hsT = sm;                    // [128][RP]  h transposed
    float* otT = hsT + 128 * RP;        // [128][RP]  out_t transposed
    float* wp  = otT + 128 * RP;        // [128][96]  q|k|v proj weights
    float* wo  = wp  + 128 * 96;        // [32][128]
    float* bo  = wo  + 32 * 128;        // [128]
    float* qs  = bo  + 128;             // [80][32]
    float* ks  = qs  + 80 * 32;
    float* vs  = ks  + 80 * 32;
    float* osT = vs  + 80 * 32;         // [32][RP]

    const int tid = threadIdx.x;
    const int b   = blockIdx.x;

    // ---- combine GEMM partials + bias + leaky, transpose into smem ----
    {
        const float* p0 = g_part + (size_t)b * (T_ * C_ * D_);
        const float* p1 = g_part + (size_t)(M_TOT * N_TOT) + (size_t)b * (T_ * C_ * D_);
        for (int f = tid; f < 10240; f += 256) {
            int r = f >> 7, d = f & 127;
            float u = p0[f] + p1[f] + Bemb[d];
            hsT[d * RP + r] = (u > 0.f) ? u : 0.2f * u;
        }
    }
    __syncthreads();

    for (int blk = 0; blk < 2; blk++) {
        for (int axis = 0; axis < 2; axis++) {
            const int s = blk * 2 + axis;

            // ---- stage weights ----
            const float4* wq4  = (const float4*)(Wq  + s * 128 * 32);
            const float4* wkv4 = (const float4*)(Wkv + s * 128 * 64);
            for (int f = tid; f < 128 * 24; f += 256) {
                int d = f / 24, q4 = f - d * 24;
                float4 v = (q4 < 8) ? wq4[d * 8 + q4] : wkv4[d * 16 + (q4 - 8)];
                *(float4*)&wp[d * 96 + q4 * 4] = v;
            }
            const float4* wo4 = (const float4*)(Wout + s * 32 * 128);
            for (int f = tid; f < 1024; f += 256) ((float4*)wo)[f] = wo4[f];
            if (tid < 128) bo[tid] = Bout[s * 128 + tid];
            __syncthreads();

            // ---- qkv projection: 80 rows x 96 cols, thread tile 8x4 ----
            if (tid < 240) {
                const int rg = tid / 24;          // 0..9  (rows rg*8..+7)
                const int cg = tid - rg * 24;     // 0..23 (cols cg*4..+3)
                ull acc[4][4];
#pragma unroll
                for (int p = 0; p < 4; p++)
#pragma unroll
                    for (int j = 0; j < 4; j++) acc[p][j] = 0ull;

                const float* hb = &hsT[rg * 8];
                const float* wb = &wp[cg * 4];
#pragma unroll 4
                for (int d = 0; d < 128; d++) {
                    float2 a0 = *(const float2*)&hb[d * RP + 0];
                    float2 a1 = *(const float2*)&hb[d * RP + 2];
                    float2 a2 = *(const float2*)&hb[d * RP + 4];
                    float2 a3 = *(const float2*)&hb[d * RP + 6];
                    float4 w  = *(const float4*)&wb[d * 96];
                    ull ap0 = pack2(a0.x, a0.y), ap1 = pack2(a1.x, a1.y);
                    ull ap2 = pack2(a2.x, a2.y), ap3 = pack2(a3.x, a3.y);
                    ull bp0 = pack2(w.x, w.x), bp1 = pack2(w.y, w.y);
                    ull bp2 = pack2(w.z, w.z), bp3 = pack2(w.w, w.w);
                    acc[0][0] = ffma2(ap0, bp0, acc[0][0]);
                    acc[0][1] = ffma2(ap0, bp1, acc[0][1]);
                    acc[0][2] = ffma2(ap0, bp2, acc[0][2]);
                    acc[0][3] = ffma2(ap0, bp3, acc[0][3]);
                    acc[1][0] = ffma2(ap1, bp0, acc[1][0]);
                    acc[1][1] = ffma2(ap1, bp1, acc[1][1]);
                    acc[1][2] = ffma2(ap1, bp2, acc[1][2]);
                    acc[1][3] = ffma2(ap1, bp3, acc[1][3]);
                    acc[2][0] = ffma2(ap2, bp0, acc[2][0]);
                    acc[2][1] = ffma2(ap2, bp1, acc[2][1]);
                    acc[2][2] = ffma2(ap2, bp2, acc[2][2]);
                    acc[2][3] = ffma2(ap2, bp3, acc[2][3]);
                    acc[3][0] = ffma2(ap3, bp0, acc[3][0]);
                    acc[3][1] = ffma2(ap3, bp1, acc[3][1]);
                    acc[3][2] = ffma2(ap3, bp2, acc[3][2]);
                    acc[3][3] = ffma2(ap3, bp3, acc[3][3]);
                }
                const int which = cg >> 3;   // 0=q, 1=k, 2=v
                float* dst = (which == 0) ? qs : (which == 1) ? ks : vs;
                const int lj = (cg & 7) * 4;
#pragma unroll
                for (int p = 0; p < 4; p++) {
                    const int r0 = rg * 8 + 2 * p;
#pragma unroll
                    for (int jc = 0; jc < 4; jc++) {
                        float2 v = unpack2(acc[p][jc]);
                        dst[r0 * 32 + lj + jc]       = v.x;
                        dst[(r0 + 1) * 32 + lj + jc] = v.y;
                    }
                }
            }
            __syncthreads();

            // ---- attention core (640 tasks) ----
            for (int o = tid; o < 640; o += 256) {
                if (axis == 0) {
                    // attend over T: task = (c, h, t), keys t' = 0..19
                    const int t  = o % 20;
                    const int ch = o / 20;
                    const int c  = ch & 3, h = ch >> 2;
                    const int r  = t * 4 + c;
                    const float* qp = &qs[r * 32 + h * 4];
                    float p[20];
                    float mx = -1e30f;
#pragma unroll
                    for (int s2 = 0; s2 < 20; s2++) {
                        const float* kp = &ks[(s2 * 4 + c) * 32 + h * 4];
                        float d = (qp[0]*kp[0] + qp[1]*kp[1] + qp[2]*kp[2] + qp[3]*kp[3]) * 0.5f;
                        p[s2] = d;
                        mx = fmaxf(mx, d);
                    }
                    float sum = 0.f;
#pragma unroll
                    for (int s2 = 0; s2 < 20; s2++) { p[s2] = __expf(p[s2] - mx); sum += p[s2]; }
                    float inv = 1.f / sum;
                    float o0 = 0.f, o1 = 0.f, o2 = 0.f, o3 = 0.f;
#pragma unroll
                    for (int s2 = 0; s2 < 20; s2++) {
                        const float* vp = &vs[(s2 * 4 + c) * 32 + h * 4];
                        float w = p[s2] * inv;
                        o0 += w * vp[0]; o1 += w * vp[1]; o2 += w * vp[2]; o3 += w * vp[3];
                    }
                    osT[(h*4 + 0) * RP + r] = o0;
                    osT[(h*4 + 1) * RP + r] = o1;
                    osT[(h*4 + 2) * RP + r] = o2;
                    osT[(h*4 + 3) * RP + r] = o3;
                } else {
                    // attend over C: task = (t, h, cq), keys c' = 0..3
                    const int cq = o & 3;
                    const int h  = (o >> 2) & 7;
                    const int t  = o >> 5;
                    const int r  = t * 4 + cq;
                    const float* qp = &qs[r * 32 + h * 4];
                    float p[4];
                    float mx = -1e30f;
#pragma unroll
                    for (int s2 = 0; s2 < 4; s2++) {
                        const float* kp = &ks[(t * 4 + s2) * 32 + h * 4];
                        float d = (qp[0]*kp[0] + qp[1]*kp[1] + qp[2]*kp[2] + qp[3]*kp[3]) * 0.5f;
                        p[s2] = d;
                        mx = fmaxf(mx, d);
                    }
                    float sum = 0.f;
#pragma unroll
                    for (int s2 = 0; s2 < 4; s2++) { p[s2] = __expf(p[s2] - mx); sum += p[s2]; }
                    float inv = 1.f / sum;
                    float o0 = 0.f, o1 = 0.f, o2 = 0.f, o3 = 0.f;
#pragma unroll
                    for (int s2 = 0; s2 < 4; s2++) {
                        const float* vp = &vs[(t * 4 + s2) * 32 + h * 4];
                        float w = p[s2] * inv;
                        o0 += w * vp[0]; o1 += w * vp[1]; o2 += w * vp[2]; o3 += w * vp[3];
                    }
                    osT[(h*4 + 0) * RP + r] = o0;
                    osT[(h*4 + 1) * RP + r] = o1;
                    osT[(h*4 + 2) * RP + r] = o2;
                    osT[(h*4 + 3) * RP + r] = o3;
                }
            }
            __syncthreads();

            // ---- output projection: 80 rows x 128 cols, thread tile 8x8 ----
            if (tid < 160) {
                const int rg = tid >> 4;          // 0..9
                const int cg = tid & 15;          // cols cg*8..+7
                ull acc[4][8];
#pragma unroll
                for (int p = 0; p < 4; p++)
#pragma unroll
                    for (int jc = 0; jc < 8; jc++) acc[p][jc] = 0ull;

                const float* ob = &osT[rg * 8];
                const float* wb = &wo[cg * 8];
#pragma unroll
                for (int j = 0; j < 32; j++) {
                    float2 a0 = *(const float2*)&ob[j * RP + 0];
                    float2 a1 = *(const float2*)&ob[j * RP + 2];
                    float2 a2 = *(const float2*)&ob[j * RP + 4];
                    float2 a3 = *(const float2*)&ob[j * RP + 6];
                    float4 w0 = *(const float4*)&wb[j * 128];
                    float4 w1 = *(const float4*)&wb[j * 128 + 4];
                    ull ap[4] = { pack2(a0.x, a0.y), pack2(a1.x, a1.y),
                                  pack2(a2.x, a2.y), pack2(a3.x, a3.y) };
                    ull bp[8] = { pack2(w0.x, w0.x), pack2(w0.y, w0.y),
                                  pack2(w0.z, w0.z), pack2(w0.w, w0.w),
                                  pack2(w1.x, w1.x), pack2(w1.y, w1.y),
                                  pack2(w1.z, w1.z), pack2(w1.w, w1.w) };
#pragma unroll
                    for (int p = 0; p < 4; p++)
#pragma unroll
                        for (int jc = 0; jc < 8; jc++)
                            acc[p][jc] = ffma2(ap[p], bp[jc], acc[p][jc]);
                }
#pragma unroll
                for (int jc = 0; jc < 8; jc++) {
                    const int n = cg * 8 + jc;
                    const float bia = bo[n];
#pragma unroll
                    for (int p = 0; p < 4; p++) {
                        float2 v = unpack2(acc[p][jc]);
                        const int r0 = rg * 8 + 2 * p;
                        if (axis == 0) {
                            otT[n * RP + r0]     = v.x + bia;
                            otT[n * RP + r0 + 1] = v.y + bia;
                        } else {
                            float u0 = v.x + bia + otT[n * RP + r0];
                            float u1 = v.y + bia + otT[n * RP + r0 + 1];
                            hsT[n * RP + r0]     = (u0 > 0.f) ? u0 : 0.2f * u0;
                            hsT[n * RP + r0 + 1] = (u1 > 0.f) ? u1 : 0.2f * u1;
                        }
                    }
                }
            }
            __syncthreads();
        }
    }

    // ---- decoder: dot(h_flat, Wd) + bias, sigmoid ----
    float acc = 0.f;
    for (int f = tid; f < 10240; f += 256) {
        int r = f >> 7, d = f & 127;
        acc += hsT[d * RP + r] * Wd[f];
    }
#pragma unroll
    for (int off = 16; off; off >>= 1) acc += __shfl_down_sync(0xffffffffu, acc, off);
    if ((tid & 31) == 0) qs[tid >> 5] = acc;   // reuse qs as scratch
    __syncthreads();
    if (tid == 0) {
        float s = 0.f;
#pragma unroll
        for (int w = 0; w < 8; w++) s += qs[w];
        s += bd[0];
        out[b] = 1.f / (1.f + __expf(-s));
    }
}

// ---------------------------------------------------------------------------
// Launch
// ---------------------------------------------------------------------------
extern "C" void kernel_launch(void* const* d_in, const int* in_sizes, int n_in,
                              void* d_out, int out_size)
{
    const float* x     = (const float*)d_in[0];
    const float* n1    = (const float*)d_in[1];
    const float* n2    = (const float*)d_in[2];
    const float* W_emb = (const float*)d_in[3];
    const float* b_emb = (const float*)d_in[4];
    const float* Wq    = (const float*)d_in[5];
    const float* Wkv   = (const float*)d_in[6];
    const float* Wout  = (const float*)d_in[7];
    const float* bout  = (const float*)d_in[8];
    const float* W_dec = (const float*)d_in[9];
    const float* b_dec = (const float*)d_in[10];
    float* out = (float*)d_out;

    cudaFuncSetAttribute(mega_kernel, cudaFuncAttributeMaxDynamicSharedMemorySize, MEGA_BYTES);

    dim3 eg(M_TOT / BM, KSPLIT);
    emb_kernel<<<eg, 256>>>(x, n1, n2, W_emb);

    mega_kernel<<<B_, 256, MEGA_BYTES>>>(Wq, Wkv, Wout, bout, b_emb, W_dec, b_dec, out);
}